// round 3
// baseline (speedup 1.0000x reference)
#include <cuda_runtime.h>
#include <math.h>

#define BATCH 8
#define CIN   128
#define H     112
#define W     112
#define COUT  256
#define OFFC  18     // 2*K*K

typedef unsigned long long ull;

// Scratch (allocation-free rule: __device__ globals)
__device__ float g_offset[BATCH * OFFC * H * W];     // (B,18,H,W)
__device__ float g_sampled[BATCH * CIN * H * W];     // (B,128,H,W)

// ---- f32x2 packed-math helpers (sm_100+; ptxas never auto-emits FFMA2) ----
__device__ __forceinline__ ull pk2(float lo, float hi) {
    ull r; asm("mov.b64 %0, {%1, %2};" : "=l"(r) : "f"(lo), "f"(hi)); return r;
}
__device__ __forceinline__ void fma2(ull& d, ull a, ull b) {
    asm("fma.rn.f32x2 %0, %1, %2, %0;" : "+l"(d) : "l"(a), "l"(b));
}
__device__ __forceinline__ float2 upk2(ull v) {
    float2 f; asm("mov.b64 {%0, %1}, %2;" : "=f"(f.x), "=f"(f.y) : "l"(v)); return f;
}

// ---------------------------------------------------------------------------
// Kernel 1: offset conv  x(B,128,H,W) * ow(18,128,3,3) + ob -> g_offset
// Block = one (b,h) row, 128 threads. 9 f32x2 accumulators (oc pairs).
// ---------------------------------------------------------------------------
#define K1_CK 16
__global__ void offset_conv_kernel(const float* __restrict__ x,
                                   const float* __restrict__ ow,
                                   const float* __restrict__ ob) {
    __shared__ __align__(16) float sW[K1_CK * 9 * OFFC];   // [ci][k][oc] (oc pairs 8B-aligned)
    __shared__ float sX[K1_CK * 3 * 114];                  // [ci][r][j], j -> col j-1
    const int h = blockIdx.x;
    const int b = blockIdx.y;
    const int tid = threadIdx.x;
    const int w = tid;

    ull acc[9];
#pragma unroll
    for (int j = 0; j < 9; j++) acc[j] = pk2(ob[2 * j], ob[2 * j + 1]);

    for (int c0 = 0; c0 < CIN; c0 += K1_CK) {
        for (int e = tid; e < K1_CK * 3 * 114; e += blockDim.x) {
            int ci  = e / (3 * 114);
            int rem = e % (3 * 114);
            int r   = rem / 114;
            int j   = rem % 114;
            int row = h - 1 + r;
            int col = j - 1;
            float v = 0.f;
            if (row >= 0 && row < H && col >= 0 && col < W)
                v = x[((b * CIN + c0 + ci) * H + row) * W + col];
            sX[e] = v;
        }
        for (int e = tid; e < K1_CK * 9 * OFFC; e += blockDim.x) {
            int ci  = e / (9 * OFFC);
            int rem = e % (9 * OFFC);
            int k   = rem / OFFC;
            int oc  = rem % OFFC;
            sW[e] = ow[(oc * CIN + c0 + ci) * 9 + k];
        }
        __syncthreads();
        if (w < W) {
            for (int ci = 0; ci < K1_CK; ci++) {
                float xv[9];
#pragma unroll
                for (int ky = 0; ky < 3; ky++)
#pragma unroll
                    for (int kx = 0; kx < 3; kx++)
                        xv[ky * 3 + kx] = sX[(ci * 3 + ky) * 114 + w + kx];
#pragma unroll
                for (int k = 0; k < 9; k++) {
                    ull xp = pk2(xv[k], xv[k]);
                    const ull* wp = reinterpret_cast<const ull*>(&sW[(ci * 9 + k) * OFFC]);
#pragma unroll
                    for (int j = 0; j < 9; j++) fma2(acc[j], xp, wp[j]);
                }
            }
        }
        __syncthreads();
    }
    if (w < W) {
#pragma unroll
        for (int j = 0; j < 9; j++) {
            float2 f = upk2(acc[j]);
            g_offset[((b * OFFC + 2 * j)     * H + h) * W + w] = f.x;
            g_offset[((b * OFFC + 2 * j + 1) * H + h) * W + w] = f.y;
        }
    }
}

// ---------------------------------------------------------------------------
// Kernel 2: deformable bilinear sampling, summed over 9 points -> g_sampled
// ---------------------------------------------------------------------------
__device__ __forceinline__ void make_corner(int yi, int xi, float wgt,
                                            int& idx, float& wt) {
    bool valid = (yi >= 0) & (yi < H) & (xi >= 0) & (xi < W);
    int yc = min(max(yi, 0), H - 1);
    int xc = min(max(xi, 0), W - 1);
    idx = yc * W + xc;
    wt = valid ? wgt : 0.f;
}

__global__ void sample_kernel(const float* __restrict__ x) {
    const int h = blockIdx.x;
    const int b = blockIdx.y;
    const int w = threadIdx.x;
    if (w >= W) return;
    const int pix = h * W + w;
    const float* offp = g_offset + (size_t)b * OFFC * H * W + pix;

    int   idx[36];
    float wt[36];
#pragma unroll
    for (int p = 0; p < 9; p++) {
        int ky = p / 3, kx = p % 3;
        float offY = offp[(size_t)p * H * W];
        float offX = offp[(size_t)(9 + p) * H * W];
        float sy = (float)(h + ky - 1) + offY;
        float sx = (float)(w + kx - 1) + offX;
        float fy0 = floorf(sy), fx0 = floorf(sx);
        int y0 = (int)fy0, x0 = (int)fx0;
        float wy = sy - fy0, wx = sx - fx0;
        make_corner(y0,     x0,     (1.f - wy) * (1.f - wx), idx[p*4+0], wt[p*4+0]);
        make_corner(y0,     x0 + 1, (1.f - wy) * wx,         idx[p*4+1], wt[p*4+1]);
        make_corner(y0 + 1, x0,     wy * (1.f - wx),         idx[p*4+2], wt[p*4+2]);
        make_corner(y0 + 1, x0 + 1, wy * wx,                 idx[p*4+3], wt[p*4+3]);
    }

    const float* xb = x + (size_t)b * CIN * H * W;
    float* outb = g_sampled + (size_t)b * CIN * H * W + pix;
#pragma unroll 2
    for (int c = 0; c < CIN; c++) {
        const float* xp = xb + (size_t)c * H * W;
        float acc = 0.f;
#pragma unroll
        for (int q = 0; q < 36; q++) acc += wt[q] * xp[idx[q]];
        outb[(size_t)c * H * W] = acc;
    }
}

// ---------------------------------------------------------------------------
// Kernel 3: main conv  g_sampled(B,128,H,W) * cw(256,128,3,3) -> out
// Block: 64 co x full 112-wide row for one (b,h). 224 threads:
//   tco in [0,16) -> 4 consecutive co; tw in [0,14) -> 8 w each.
// Accumulators = 4co x 4 f32x2 (w-pairs). Weights pre-duplicated (w,w) in smem
// so FFMA2 b-operands come straight from LDS.128 (zero pack cost).
// ---------------------------------------------------------------------------
#define CO_TILE 64
#define K3_CK   8
#define RS      116                      // padded sIn row stride (16B-aligned rows)
__global__ void __launch_bounds__(224) main_conv_kernel(
        const float* __restrict__ cw, float* __restrict__ out) {
    __shared__ __align__(16) float sIn[K3_CK * 3 * RS];     // [ci][r][j], col j-1
    __shared__ __align__(16) ull   sWt2[K3_CK * 9 * CO_TILE]; // [ci][k][co] dup pairs
    const int cog = blockIdx.x;
    const int h   = blockIdx.y;
    const int b   = blockIdx.z;
    const int tid = threadIdx.x;
    const int tco = tid / 14;            // 0..15 -> 4 co each
    const int tw  = tid % 14;            // 0..13 -> 8 w each
    const int wbase = tw * 8;
    const int co_base = cog * CO_TILE;

    ull acc[4][4];
#pragma unroll
    for (int r = 0; r < 4; r++)
#pragma unroll
        for (int i = 0; i < 4; i++) acc[r][i] = 0ULL;

    for (int c0 = 0; c0 < CIN; c0 += K3_CK) {
        for (int e = tid; e < K3_CK * 3 * RS; e += 224) {
            int ci  = e / (3 * RS);
            int rem = e % (3 * RS);
            int r   = rem / RS;
            int j   = rem % RS;
            int row = h - 1 + r;
            int col = j - 1;
            float v = 0.f;
            if (row >= 0 && row < H && col >= 0 && col < W)
                v = g_sampled[((b * CIN + c0 + ci) * H + row) * W + col];
            sIn[e] = v;
        }
        for (int e = tid; e < K3_CK * 9 * CO_TILE; e += 224) {
            int ci  = e / (9 * CO_TILE);
            int rem = e % (9 * CO_TILE);
            int k   = rem / CO_TILE;
            int co  = rem % CO_TILE;
            float v = cw[((co_base + co) * CIN + c0 + ci) * 9 + k];
            sWt2[e] = pk2(v, v);
        }
        __syncthreads();

#pragma unroll
        for (int ci = 0; ci < K3_CK; ci++) {
#pragma unroll
            for (int ky = 0; ky < 3; ky++) {
                const float* vp = &sIn[(ci * 3 + ky) * RS + wbase];
                float4 va = *reinterpret_cast<const float4*>(vp);
                float4 vb = *reinterpret_cast<const float4*>(vp + 4);
                float2 vc = *reinterpret_cast<const float2*>(vp + 8);
                float v0 = va.x, v1 = va.y, v2 = va.z, v3 = va.w;
                float v4 = vb.x, v5 = vb.y, v6 = vb.z, v7 = vb.w;
                float v8 = vc.x, v9 = vc.y;
                // shifted input pairs for kx = 0,1,2
                ull p0[4] = { pk2(v0, v1), pk2(v2, v3), pk2(v4, v5), pk2(v6, v7) };
                ull p1[4] = { pk2(v1, v2), pk2(v3, v4), pk2(v5, v6), pk2(v7, v8) };
                ull p2[4] = { pk2(v2, v3), pk2(v4, v5), pk2(v6, v7), pk2(v8, v9) };
#pragma unroll
                for (int kx = 0; kx < 3; kx++) {
                    const ull* pp = (kx == 0) ? p0 : (kx == 1) ? p1 : p2;
                    const ulonglong2* wq = reinterpret_cast<const ulonglong2*>(
                        &sWt2[(ci * 9 + ky * 3 + kx) * CO_TILE + tco * 4]);
                    ulonglong2 w01 = wq[0];
                    ulonglong2 w23 = wq[1];
                    ull wp0 = w01.x, wp1 = w01.y, wp2 = w23.x, wp3 = w23.y;
#pragma unroll
                    for (int i = 0; i < 4; i++) {
                        fma2(acc[0][i], pp[i], wp0);
                        fma2(acc[1][i], pp[i], wp1);
                        fma2(acc[2][i], pp[i], wp2);
                        fma2(acc[3][i], pp[i], wp3);
                    }
                }
            }
        }
        __syncthreads();
    }

#pragma unroll
    for (int r = 0; r < 4; r++) {
        int co = co_base + tco * 4 + r;
        float* op = out + (((size_t)b * COUT + co) * H + h) * W + wbase;
        float2 f0 = upk2(acc[r][0]);
        float2 f1 = upk2(acc[r][1]);
        float2 f2 = upk2(acc[r][2]);
        float2 f3 = upk2(acc[r][3]);
        float4 o0 = make_float4(f0.x, f0.y, f1.x, f1.y);
        float4 o1 = make_float4(f2.x, f2.y, f3.x, f3.y);
        *reinterpret_cast<float4*>(op)     = o0;
        *reinterpret_cast<float4*>(op + 4) = o1;
    }
}

// ---------------------------------------------------------------------------
extern "C" void kernel_launch(void* const* d_in, const int* in_sizes, int n_in,
                              void* d_out, int out_size) {
    const float* x  = (const float*)d_in[0];   // (8,128,112,112)
    const float* ow = (const float*)d_in[1];   // (18,128,3,3)
    const float* ob = (const float*)d_in[2];   // (18)
    const float* cw = (const float*)d_in[3];   // (256,128,3,3)
    float* out = (float*)d_out;                // (8,256,112,112)

    dim3 grid_row(H, BATCH);
    offset_conv_kernel<<<grid_row, 128>>>(x, ow, ob);
    sample_kernel<<<grid_row, 112>>>(x);
    dim3 grid_conv(COUT / CO_TILE, H, BATCH);
    main_conv_kernel<<<grid_conv, 224>>>(cw, out);
}

// round 6
// speedup vs baseline: 3.1927x; 3.1927x over previous
#include <cuda_runtime.h>
#include <math.h>
#include <stdint.h>

#define BATCH 8
#define CIN   128
#define H     112
#define W     112
#define COUT  256
#define OFFC  18
#define HW    (H * W)
#define KCH   36        // k chunks of 32 (1152 total)

// ---------------------------------------------------------------------------
// Scratch (allocation-free rule: __device__ globals)
// ---------------------------------------------------------------------------
__device__ float g_offset[BATCH * OFFC * H * W];
__device__ float g_sampled[BATCH * CIN * H * W];
// tf32 weights: [cog(2)][chunk(36)][m(128)][k(32)]
__device__ __align__(16) unsigned int g_wpre[2 * KCH * 4096];

// ---------------------------------------------------------------------------
// helpers
// ---------------------------------------------------------------------------
__device__ __forceinline__ uint32_t smem_u32(const void* p) {
    uint32_t a;
    asm("{ .reg .u64 t; cvta.to.shared.u64 t, %1; cvt.u32.u64 %0, t; }" : "=r"(a) : "l"(p));
    return a;
}
__device__ __forceinline__ unsigned int to_tf32(float v) {
    unsigned int t; asm("cvt.rna.tf32.f32 %0, %1;" : "=r"(t) : "f"(v)); return t;
}
__device__ __forceinline__ void cp16(uint32_t dst, const void* src) {
    asm volatile("cp.async.cg.shared.global [%0], [%1], 16;" :: "r"(dst), "l"(src) : "memory");
}
#define CP_COMMIT() asm volatile("cp.async.commit_group;" ::: "memory")
#define CP_WAIT0()  asm volatile("cp.async.wait_group 0;" ::: "memory")

__device__ __forceinline__ void mma_tf32(float* d, const unsigned* a, const unsigned* b) {
    asm volatile(
        "mma.sync.aligned.m16n8k8.row.col.f32.tf32.tf32.f32 "
        "{%0,%1,%2,%3}, {%4,%5,%6,%7}, {%8,%9}, {%0,%1,%2,%3};"
        : "+f"(d[0]), "+f"(d[1]), "+f"(d[2]), "+f"(d[3])
        : "r"(a[0]), "r"(a[1]), "r"(a[2]), "r"(a[3]), "r"(b[0]), "r"(b[1]));
}

// ---------------------------------------------------------------------------
// Kernel 1: offset conv (unchanged)
// ---------------------------------------------------------------------------
#define K1_CK 16
__global__ void offset_conv_kernel(const float* __restrict__ x,
                                   const float* __restrict__ ow,
                                   const float* __restrict__ ob) {
    __shared__ float sW[K1_CK * 9 * OFFC];
    __shared__ float sX[K1_CK * 3 * 114];
    const int h = blockIdx.x;
    const int b = blockIdx.y;
    const int tid = threadIdx.x;
    const int w = tid;

    float acc[OFFC];
#pragma unroll
    for (int oc = 0; oc < OFFC; oc++) acc[oc] = ob[oc];

    for (int c0 = 0; c0 < CIN; c0 += K1_CK) {
        for (int e = tid; e < K1_CK * 3 * 114; e += blockDim.x) {
            int ci = e / (3 * 114), rem = e % (3 * 114);
            int r = rem / 114, j = rem % 114;
            int row = h - 1 + r, col = j - 1;
            float v = 0.f;
            if (row >= 0 && row < H && col >= 0 && col < W)
                v = x[((b * CIN + c0 + ci) * H + row) * W + col];
            sX[e] = v;
        }
        for (int e = tid; e < K1_CK * 9 * OFFC; e += blockDim.x) {
            int ci = e / (9 * OFFC), rem = e % (9 * OFFC);
            int k = rem / OFFC, oc = rem % OFFC;
            sW[e] = ow[(oc * CIN + c0 + ci) * 9 + k];
        }
        __syncthreads();
        if (w < W) {
            for (int ci = 0; ci < K1_CK; ci++) {
                float xv[9];
#pragma unroll
                for (int ky = 0; ky < 3; ky++)
#pragma unroll
                    for (int kx = 0; kx < 3; kx++)
                        xv[ky * 3 + kx] = sX[(ci * 3 + ky) * 114 + w + kx];
#pragma unroll
                for (int k = 0; k < 9; k++) {
                    float xvk = xv[k];
#pragma unroll
                    for (int oc = 0; oc < OFFC; oc++)
                        acc[oc] += xvk * sW[(ci * 9 + k) * OFFC + oc];
                }
            }
        }
        __syncthreads();
    }
    if (w < W) {
#pragma unroll
        for (int oc = 0; oc < OFFC; oc++)
            g_offset[((b * OFFC + oc) * H + h) * W + w] = acc[oc];
    }
}

// ---------------------------------------------------------------------------
// Kernel 2: deformable bilinear sampling (unchanged)
// ---------------------------------------------------------------------------
__device__ __forceinline__ void make_corner(int yi, int xi, float wgt,
                                            int& idx, float& wt) {
    bool valid = (yi >= 0) & (yi < H) & (xi >= 0) & (xi < W);
    int yc = min(max(yi, 0), H - 1);
    int xc = min(max(xi, 0), W - 1);
    idx = yc * W + xc;
    wt = valid ? wgt : 0.f;
}

__global__ void sample_kernel(const float* __restrict__ x) {
    const int h = blockIdx.x;
    const int b = blockIdx.y;
    const int w = threadIdx.x;
    if (w >= W) return;
    const int pix = h * W + w;
    const float* offp = g_offset + (size_t)b * OFFC * H * W + pix;

    int idx[36]; float wt[36];
#pragma unroll
    for (int p = 0; p < 9; p++) {
        int ky = p / 3, kx = p % 3;
        float offY = offp[(size_t)p * H * W];
        float offX = offp[(size_t)(9 + p) * H * W];
        float sy = (float)(h + ky - 1) + offY;
        float sx = (float)(w + kx - 1) + offX;
        float fy0 = floorf(sy), fx0 = floorf(sx);
        int y0 = (int)fy0, x0 = (int)fx0;
        float wy = sy - fy0, wx = sx - fx0;
        make_corner(y0,     x0,     (1.f - wy) * (1.f - wx), idx[p*4+0], wt[p*4+0]);
        make_corner(y0,     x0 + 1, (1.f - wy) * wx,         idx[p*4+1], wt[p*4+1]);
        make_corner(y0 + 1, x0,     wy * (1.f - wx),         idx[p*4+2], wt[p*4+2]);
        make_corner(y0 + 1, x0 + 1, wy * wx,                 idx[p*4+3], wt[p*4+3]);
    }

    const float* xb = x + (size_t)b * CIN * H * W;
    float* outb = g_sampled + (size_t)b * CIN * H * W + pix;
#pragma unroll 2
    for (int c = 0; c < CIN; c++) {
        const float* xp = xb + (size_t)c * H * W;
        float acc = 0.f;
#pragma unroll
        for (int q = 0; q < 36; q++) acc += wt[q] * xp[idx[q]];
        outb[(size_t)c * H * W] = acc;
    }
}

// ---------------------------------------------------------------------------
// Kernel 2.5: weight prep — tf32 convert into [cog][chunk][m][k]
// chunk c: pos = c/4 (ky*3+kx), ci0 = (c%4)*32
// ---------------------------------------------------------------------------
__global__ void prep_w_kernel(const float* __restrict__ cw) {
    const int t = blockIdx.x;           // 0..71
    const int cog = t / KCH;
    const int c = t % KCH;
    const int pos = c >> 2;
    const int ci0 = (c & 3) << 5;
    unsigned int* dst = g_wpre + (size_t)t * 4096;
    for (int e = threadIdx.x; e < 4096; e += blockDim.x) {
        int m = e >> 5, kk = e & 31;
        int co = cog * 128 + m;
        dst[e] = to_tf32(cw[(co * CIN + ci0 + kk) * 9 + pos]);
    }
}

// ---------------------------------------------------------------------------
// Kernel 3: main conv via mma.sync tf32 implicit GEMM.
// CTA = (cog, h, b): M=128 co, N=112 pixels, K=1152 in 36 chunks of 32.
// 8 warps = 4(M) x 2(N); warp tile 32co x 56w = 2x7 m16n8k8 MMAs per k8.
// smem strides padded to 36 floats -> conflict-free fragment loads.
// ---------------------------------------------------------------------------
#define SA_BUF   18432u   // 128 rows * 36 floats * 4B
#define SB_BASE  36864u
#define SB_BUF   16128u   // 112 rows * 36 floats * 4B
#define SMEM_TOT 69120u

__device__ __forceinline__ void copyA(uint32_t sbase, int bufsel,
                                      const unsigned int* src, int tid) {
#pragma unroll
    for (int p = 0; p < 4; p++) {
        int ci = tid + p * 256;             // 16B chunk index, 1024 total
        int m = ci >> 3, part = ci & 7;
        uint32_t dst = sbase + bufsel * SA_BUF + (uint32_t)(m * 144 + part * 16);
        cp16(dst, src + ci * 4);
    }
}

__device__ __forceinline__ void loadB(const float* __restrict__ sampb,
                                      int h, int c, int wid, int lane, float* bv) {
    const int pos = c >> 2;
    const int ci0 = (c & 3) << 5;
    const int ky = pos / 3, kx = pos % 3;
    const int hrow = h + ky - 1;
    const bool rowok = (hrow >= 0) && (hrow < H);
#pragma unroll
    for (int q = 0; q < 4; q++) {
        const float* rp = sampb + (size_t)(ci0 + wid + q * 8) * HW + hrow * W;
#pragma unroll
        for (int nb = 0; nb < 4; nb++) {
            int n = lane + nb * 32;
            int wi = n + kx - 1;
            float v = 0.f;
            if (rowok && n < 112 && wi >= 0 && wi < W) v = rp[wi];
            bv[q * 4 + nb] = v;
        }
    }
}

__device__ __forceinline__ void stsB(float* sBbuf, int wid, int lane, const float* bv) {
#pragma unroll
    for (int q = 0; q < 4; q++)
#pragma unroll
        for (int nb = 0; nb < 4; nb++) {
            int n = lane + nb * 32;
            if (n < 112)
                sBbuf[n * 36 + wid + q * 8] = __uint_as_float(to_tf32(bv[q * 4 + nb]));
        }
}

__global__ void __launch_bounds__(256) conv_mma_kernel(float* __restrict__ out) {
    extern __shared__ char smem[];
    float* sA = (float*)smem;                  // [2][128][36]
    float* sB = (float*)(smem + SB_BASE);      // [2][112][36]
    const uint32_t sbase = smem_u32(smem);

    const int tid = threadIdx.x;
    const int wid = tid >> 5;
    const int lane = tid & 31;
    const int warp_m = wid & 3;     // co group of 32
    const int warp_n = wid >> 2;    // pixel group of 56
    const int tr = lane >> 2;
    const int tc = lane & 3;

    const int cog = blockIdx.x;
    const int h   = blockIdx.y;
    const int b   = blockIdx.z;
    const float* sampb = g_sampled + (size_t)b * CIN * HW;
    const unsigned int* wsrc = g_wpre + (size_t)cog * KCH * 4096;

    float acc[2][7][4];
#pragma unroll
    for (int mt = 0; mt < 2; mt++)
#pragma unroll
        for (int j = 0; j < 7; j++)
#pragma unroll
            for (int q = 0; q < 4; q++) acc[mt][j][q] = 0.f;

    float bv[16];
    // prologue: chunk 0 -> buf 0
    copyA(sbase, 0, wsrc, tid);
    CP_COMMIT();
    loadB(sampb, h, 0, wid, lane, bv);
    CP_WAIT0();
    stsB(sB, wid, lane, bv);
    __syncthreads();

    for (int c = 0; c < KCH; c++) {
        const int buf = c & 1;
        const bool more = (c + 1 < KCH);
        if (more) {
            copyA(sbase, buf ^ 1, wsrc + (size_t)(c + 1) * 4096, tid);
            CP_COMMIT();
            loadB(sampb, h, c + 1, wid, lane, bv);
        }
        // compute chunk c
        {
            const float* Ab = sA + buf * (SA_BUF / 4);
            const float* Bb = sB + buf * (SB_BUF / 4);
#pragma unroll
            for (int ks = 0; ks < 4; ks++) {
                unsigned a[2][4];
#pragma unroll
                for (int mt = 0; mt < 2; mt++) {
                    int r0 = warp_m * 32 + mt * 16 + tr;
                    a[mt][0] = __float_as_uint(Ab[r0 * 36 + ks * 8 + tc]);
                    a[mt][1] = __float_as_uint(Ab[(r0 + 8) * 36 + ks * 8 + tc]);
                    a[mt][2] = __float_as_uint(Ab[r0 * 36 + ks * 8 + tc + 4]);
                    a[mt][3] = __float_as_uint(Ab[(r0 + 8) * 36 + ks * 8 + tc + 4]);
                }
                unsigned bf[7][2];
#pragma unroll
                for (int j = 0; j < 7; j++) {
                    int n0 = warp_n * 56 + j * 8 + tr;
                    bf[j][0] = __float_as_uint(Bb[n0 * 36 + ks * 8 + tc]);
                    bf[j][1] = __float_as_uint(Bb[n0 * 36 + ks * 8 + tc + 4]);
                }
#pragma unroll
                for (int mt = 0; mt < 2; mt++)
#pragma unroll
                    for (int j = 0; j < 7; j++)
                        mma_tf32(acc[mt][j], a[mt], bf[j]);
            }
        }
        if (more) {
            CP_WAIT0();
            stsB(sB + (buf ^ 1) * (SB_BUF / 4), wid, lane, bv);
        }
        __syncthreads();
    }

    // epilogue
#pragma unroll
    for (int mt = 0; mt < 2; mt++) {
        int r = warp_m * 32 + mt * 16 + tr;
        int co = cog * 128 + r;
#pragma unroll
        for (int j = 0; j < 7; j++) {
            int w0 = warp_n * 56 + j * 8 + tc * 2;
            float* op = out + (((size_t)b * COUT + co) * H + h) * W + w0;
            *reinterpret_cast<float2*>(op) = make_float2(acc[mt][j][0], acc[mt][j][1]);
            float* op2 = op + (size_t)8 * H * W;   // co + 8
            *reinterpret_cast<float2*>(op2) = make_float2(acc[mt][j][2], acc[mt][j][3]);
        }
    }
}

// ---------------------------------------------------------------------------
extern "C" void kernel_launch(void* const* d_in, const int* in_sizes, int n_in,
                              void* d_out, int out_size) {
    const float* x  = (const float*)d_in[0];   // (8,128,112,112)
    const float* ow = (const float*)d_in[1];   // (18,128,3,3)
    const float* ob = (const float*)d_in[2];   // (18)
    const float* cw = (const float*)d_in[3];   // (256,128,3,3)
    float* out = (float*)d_out;                // (8,256,112,112)

    cudaFuncSetAttribute(conv_mma_kernel,
                         cudaFuncAttributeMaxDynamicSharedMemorySize, SMEM_TOT);

    prep_w_kernel<<<2 * KCH, 256>>>(cw);
    dim3 grid_row(H, BATCH);
    offset_conv_kernel<<<grid_row, 128>>>(x, ow, ob);
    sample_kernel<<<grid_row, 112>>>(x);
    dim3 grid_conv(2, H, BATCH);
    conv_mma_kernel<<<grid_conv, 256, SMEM_TOT>>>(out);
}